// round 1
// baseline (speedup 1.0000x reference)
#include <cuda_runtime.h>

// ---------------------------------------------------------------------------
// RelGAT, 2 layers, restructured:
//   score_e = <h[dst], hW1[src]> + <g[dst], efeat_e>,  g = h @ W1^T, hW1 = h@W1+b1
//   neigh_d = ( sum_e w_e hW1[src_e]  +  (sum_e w_e efeat_e) @ W1 ) / denom_d
// -> no [E,D]x[D,D] GEMM; only node-level GEMMs + two streaming edge passes.
// ---------------------------------------------------------------------------

namespace {
constexpr int    NN  = 50000;
constexpr int    NE  = 600000;
constexpr int    DIM = 128;
constexpr size_t ND  = (size_t)NN * DIM;        // 6,400,000
constexpr float  NEG_SLOPE = 0.22916666666666666f;  // (1/8 + 1/3)/2

// scratch layout (in floats)
constexpr size_t O_HW1  = 0;
constexpr size_t O_G    = 1 * ND;
constexpr size_t O_SELF = 2 * ND;
constexpr size_t O_ISO  = 3 * ND;
constexpr size_t O_WSUM = 4 * ND;
constexpr size_t O_S    = 5 * ND;
constexpr size_t O_SW1  = 6 * ND;
constexpr size_t O_H1   = 7 * ND;
constexpr size_t O_SCORE = 8 * ND;              // NE floats
constexpr size_t O_SMAX  = O_SCORE + NE;        // NN (as unsigned)
constexpr size_t O_DEN   = O_SMAX + NN;         // NN
constexpr size_t O_DEG   = O_DEN + NN;          // NN (as int)
constexpr size_t O_W1T   = O_DEG + NN;          // 128*128
constexpr size_t SCRATCH = O_W1T + (size_t)DIM * DIM;
}  // namespace

__device__ float g_scratch[SCRATCH];

// ---------------------------------------------------------------------------
// SGEMM: C[M,128] = A[M,128] @ B[128,128] (+bias), fp32.
// BM=128, BN=128, BK=8, 256 threads, 8x8 microtile.
// ---------------------------------------------------------------------------
__global__ __launch_bounds__(256) void sgemm128(
    const float* __restrict__ A, const float* __restrict__ B,
    const float* __restrict__ bias, float* __restrict__ C, int M)
{
    __shared__ float As[8][132];   // padded to kill STS bank conflicts, 16B-aligned rows
    __shared__ float Bs[8][128];

    const int tid  = threadIdx.x;
    const int row0 = blockIdx.x * 128;
    const int tx   = tid & 15;         // 0..15 -> 8 output cols each
    const int ty   = tid >> 4;         // 0..15 -> 8 output rows each
    const int ar   = tid >> 1;         // A-tile row to load (0..127)
    const int ak   = (tid & 1) * 4;    // A-tile k-offset (0 or 4)
    const int bk   = tid >> 5;         // B-tile k row (0..7)
    const int bc   = (tid & 31) * 4;   // B-tile col (0..124)
    const int grow = row0 + ar;

    float acc[8][8];
#pragma unroll
    for (int i = 0; i < 8; ++i)
#pragma unroll
        for (int j = 0; j < 8; ++j) acc[i][j] = 0.f;

    for (int k0 = 0; k0 < 128; k0 += 8) {
        float4 av = make_float4(0.f, 0.f, 0.f, 0.f);
        if (grow < M)
            av = *reinterpret_cast<const float4*>(A + (size_t)grow * 128 + k0 + ak);
        As[ak + 0][ar] = av.x;
        As[ak + 1][ar] = av.y;
        As[ak + 2][ar] = av.z;
        As[ak + 3][ar] = av.w;
        *reinterpret_cast<float4*>(&Bs[bk][bc]) =
            *reinterpret_cast<const float4*>(B + (size_t)(k0 + bk) * 128 + bc);
        __syncthreads();

#pragma unroll
        for (int k = 0; k < 8; ++k) {
            float a[8], b[8];
            reinterpret_cast<float4*>(a)[0] = *reinterpret_cast<const float4*>(&As[k][ty * 8]);
            reinterpret_cast<float4*>(a)[1] = *reinterpret_cast<const float4*>(&As[k][ty * 8 + 4]);
            reinterpret_cast<float4*>(b)[0] = *reinterpret_cast<const float4*>(&Bs[k][tx * 8]);
            reinterpret_cast<float4*>(b)[1] = *reinterpret_cast<const float4*>(&Bs[k][tx * 8 + 4]);
#pragma unroll
            for (int i = 0; i < 8; ++i)
#pragma unroll
                for (int j = 0; j < 8; ++j)
                    acc[i][j] = fmaf(a[i], b[j], acc[i][j]);
        }
        __syncthreads();
    }

    float4 bv0 = make_float4(0.f, 0.f, 0.f, 0.f);
    float4 bv1 = make_float4(0.f, 0.f, 0.f, 0.f);
    if (bias) {
        bv0 = *reinterpret_cast<const float4*>(bias + tx * 8);
        bv1 = *reinterpret_cast<const float4*>(bias + tx * 8 + 4);
    }
#pragma unroll
    for (int i = 0; i < 8; ++i) {
        int r = row0 + ty * 8 + i;
        if (r < M) {
            float4 c0 = make_float4(acc[i][0] + bv0.x, acc[i][1] + bv0.y,
                                    acc[i][2] + bv0.z, acc[i][3] + bv0.w);
            float4 c1 = make_float4(acc[i][4] + bv1.x, acc[i][5] + bv1.y,
                                    acc[i][6] + bv1.z, acc[i][7] + bv1.w);
            *reinterpret_cast<float4*>(C + (size_t)r * 128 + tx * 8)     = c0;
            *reinterpret_cast<float4*>(C + (size_t)r * 128 + tx * 8 + 4) = c1;
        }
    }
}

// ---------------------------------------------------------------------------
// small helpers
// ---------------------------------------------------------------------------
__global__ void transpose128(const float* __restrict__ W, float* __restrict__ Wt)
{
    int i = blockIdx.x * 256 + threadIdx.x;   // 16384 total
    int r = i >> 7, c = i & 127;
    Wt[c * 128 + r] = W[i];
}

__global__ void zero_int_kernel(int* p, int n)
{
    int i = blockIdx.x * blockDim.x + threadIdx.x;
    if (i < n) p[i] = 0;
}

__global__ void deg_kernel(const int* __restrict__ dst, int* __restrict__ deg)
{
    int e = blockIdx.x * blockDim.x + threadIdx.x;
    if (e < NE) atomicAdd(deg + dst[e], 1);
}

__global__ void init_layer_kernel(float* __restrict__ wsumh, float* __restrict__ sbuf,
                                  float* __restrict__ denom, unsigned int* __restrict__ smax)
{
    size_t i = (size_t)blockIdx.x * blockDim.x + threadIdx.x;
    if (i < ND) { wsumh[i] = 0.f; sbuf[i] = 0.f; }
    if (i < NN) { denom[i] = 0.f; smax[i] = 0u; }
}

// ---------------------------------------------------------------------------
// pass 1: per-edge score + segment max.  One warp per edge.
// ---------------------------------------------------------------------------
__global__ __launch_bounds__(256) void pass1_kernel(
    const float* __restrict__ h, const float* __restrict__ hW1,
    const float* __restrict__ g, const float* __restrict__ ef,
    const int* __restrict__ src, const int* __restrict__ dst,
    float* __restrict__ score, unsigned int* __restrict__ smax)
{
    int gt = blockIdx.x * blockDim.x + threadIdx.x;
    int e = gt >> 5;
    if (e >= NE) return;
    int lane = gt & 31;
    int s = __ldg(src + e), d = __ldg(dst + e);

    float4 hd = __ldg(reinterpret_cast<const float4*>(h)   + d * 32 + lane);
    float4 hw = __ldg(reinterpret_cast<const float4*>(hW1) + s * 32 + lane);
    float4 gd = __ldg(reinterpret_cast<const float4*>(g)   + d * 32 + lane);
    float4 ev = __ldg(reinterpret_cast<const float4*>(ef)  + (size_t)e * 32 + lane);

    float p = hd.x * hw.x + hd.y * hw.y + hd.z * hw.z + hd.w * hw.w
            + gd.x * ev.x + gd.y * ev.y + gd.z * ev.z + gd.w * ev.w;
#pragma unroll
    for (int o = 16; o > 0; o >>= 1) p += __shfl_xor_sync(0xffffffffu, p, o);

    if (lane == 0) {
        score[e] = p;
        unsigned u = __float_as_uint(p);
        u = (u & 0x80000000u) ? ~u : (u | 0x80000000u);   // order-preserving encode
        atomicMax(smax + d, u);
    }
}

// ---------------------------------------------------------------------------
// pass 2: w = exp(score - smax); scatter w*hW1[src] and w*efeat via v4 red.
// ---------------------------------------------------------------------------
__device__ __forceinline__ void red4(float* p, float a, float b, float c, float d)
{
    asm volatile("red.global.add.v4.f32 [%0], {%1,%2,%3,%4};"
                 :: "l"(p), "f"(a), "f"(b), "f"(c), "f"(d) : "memory");
}

__global__ __launch_bounds__(256) void pass2_kernel(
    const float* __restrict__ hW1, const float* __restrict__ ef,
    const int* __restrict__ src, const int* __restrict__ dst,
    const float* __restrict__ score, const unsigned int* __restrict__ smax,
    float* __restrict__ denom, float* __restrict__ wsumh, float* __restrict__ sbuf)
{
    int gt = blockIdx.x * blockDim.x + threadIdx.x;
    int e = gt >> 5;
    if (e >= NE) return;
    int lane = gt & 31;
    int s = __ldg(src + e), d = __ldg(dst + e);

    unsigned mu = __ldg(smax + d);
    float mx = (mu & 0x80000000u) ? __uint_as_float(mu ^ 0x80000000u)
                                  : __uint_as_float(~mu);
    float w = __expf(__ldg(score + e) - mx);
    if (lane == 0) atomicAdd(denom + d, w);

    float4 hw = __ldg(reinterpret_cast<const float4*>(hW1) + s * 32 + lane);
    float4 ev = __ldg(reinterpret_cast<const float4*>(ef)  + (size_t)e * 32 + lane);

    red4(wsumh + (size_t)d * 128 + lane * 4, w * hw.x, w * hw.y, w * hw.z, w * hw.w);
    red4(sbuf  + (size_t)d * 128 + lane * 4, w * ev.x, w * ev.y, w * ev.z, w * ev.w);
}

// ---------------------------------------------------------------------------
// finalize: out = leaky( (deg==0 ? iso : self) + (wsumh + s@W1)/max(denom,1e-30) )
// ---------------------------------------------------------------------------
__device__ __forceinline__ float lrelu(float v) { return v >= 0.f ? v : v * NEG_SLOPE; }

__global__ __launch_bounds__(256) void finalize_kernel(
    const float* __restrict__ wsumh, const float* __restrict__ sW1,
    const float* __restrict__ denom, const int* __restrict__ deg,
    const float* __restrict__ selfm, const float* __restrict__ isom,
    float* __restrict__ out)
{
    int i = blockIdx.x * blockDim.x + threadIdx.x;   // over NN*32 float4s
    if (i >= NN * 32) return;
    int n = i >> 5;

    float4 ws = __ldg(reinterpret_cast<const float4*>(wsumh) + i);
    float4 sv = __ldg(reinterpret_cast<const float4*>(sW1)   + i);
    float inv = 1.0f / fmaxf(__ldg(denom + n), 1e-30f);
    const float4* smp = (__ldg(deg + n) == 0)
                            ? reinterpret_cast<const float4*>(isom)
                            : reinterpret_cast<const float4*>(selfm);
    float4 sm = __ldg(smp + i);

    float4 r;
    r.x = lrelu(sm.x + (ws.x + sv.x) * inv);
    r.y = lrelu(sm.y + (ws.y + sv.y) * inv);
    r.z = lrelu(sm.z + (ws.z + sv.z) * inv);
    r.w = lrelu(sm.w + (ws.w + sv.w) * inv);
    reinterpret_cast<float4*>(out)[i] = r;
}

// ---------------------------------------------------------------------------
// launch
// ---------------------------------------------------------------------------
extern "C" void kernel_launch(void* const* d_in, const int* in_sizes, int n_in,
                              void* d_out, int out_size)
{
    const float* node = (const float*)d_in[0];
    const float* ef   = (const float*)d_in[1];
    const int*   src  = (const int*)d_in[2];
    const int*   dst  = (const int*)d_in[3];
    const float* W1[2] = {(const float*)d_in[4],  (const float*)d_in[10]};
    const float* B1[2] = {(const float*)d_in[5],  (const float*)d_in[11]};
    const float* W2[2] = {(const float*)d_in[6],  (const float*)d_in[12]};
    const float* B2[2] = {(const float*)d_in[7],  (const float*)d_in[13]};
    const float* W3[2] = {(const float*)d_in[8],  (const float*)d_in[14]};
    const float* B3[2] = {(const float*)d_in[9],  (const float*)d_in[15]};

    float* base = nullptr;
    cudaGetSymbolAddress((void**)&base, g_scratch);

    float*        hW1   = base + O_HW1;
    float*        g     = base + O_G;
    float*        selfm = base + O_SELF;
    float*        isom  = base + O_ISO;
    float*        wsumh = base + O_WSUM;
    float*        sbuf  = base + O_S;
    float*        sW1   = base + O_SW1;
    float*        h1    = base + O_H1;
    float*        score = base + O_SCORE;
    unsigned int* smax  = (unsigned int*)(base + O_SMAX);
    float*        denom = base + O_DEN;
    int*          deg   = (int*)(base + O_DEG);
    float*        W1t   = base + O_W1T;

    // degree (layer-independent)
    zero_int_kernel<<<(NN + 255) / 256, 256>>>(deg, NN);
    deg_kernel<<<(NE + 255) / 256, 256>>>(dst, deg);

    const int gemmGrid = (NN + 127) / 128;                 // 391
    const int edgeGrid = (int)(((size_t)NE * 32 + 255) / 256);  // 75000
    const int initGrid = (int)((ND + 255) / 256);

    const float* h = node;
    float* out_l[2] = {h1, (float*)d_out};

    for (int l = 0; l < 2; ++l) {
        transpose128<<<64, 256>>>(W1[l], W1t);
        init_layer_kernel<<<initGrid, 256>>>(wsumh, sbuf, denom, smax);

        sgemm128<<<gemmGrid, 256>>>(h, W1[l], B1[l], hW1,   NN);
        sgemm128<<<gemmGrid, 256>>>(h, W1t,   nullptr, g,   NN);
        sgemm128<<<gemmGrid, 256>>>(h, W2[l], B2[l], selfm, NN);
        sgemm128<<<gemmGrid, 256>>>(h, W3[l], B3[l], isom,  NN);

        pass1_kernel<<<edgeGrid, 256>>>(h, hW1, g, ef, src, dst, score, smax);
        pass2_kernel<<<edgeGrid, 256>>>(hW1, ef, src, dst, score, smax, denom, wsumh, sbuf);

        sgemm128<<<gemmGrid, 256>>>(sbuf, W1[l], nullptr, sW1, NN);

        finalize_kernel<<<(NN * 32 + 255) / 256, 256>>>(wsumh, sW1, denom, deg,
                                                        selfm, isom, out_l[l]);
        h = h1;
    }
}

// round 5
// speedup vs baseline: 1.2541x; 1.2541x over previous
#include <cuda_runtime.h>
#include <cuda_bf16.h>
#include <cstdint>

// ---------------------------------------------------------------------------
// RelGAT restructured:
//   score_e = <h[dst], hW1[src]> + <g[dst], efeat_e>,  g = h@W1^T, hW1 = h@W1+b1
//   neigh_d = ( sum w_e hW1[src] + (sum w_e efeat_e)@W1 ) / denom
// GEMMs: mma.sync m16n8k16 bf16 (family-portable tensor path; tcgen05 is
// rejected because the harness compiles PTX for compute_103 without the 'a').
// bf16x3 emulation: fp32 -> bf16 hi/lo, groups hh + hl + lh, fp32 accumulate.
// ---------------------------------------------------------------------------

namespace {
constexpr int    NN  = 50000;
constexpr int    NE  = 600000;
constexpr size_t ND  = (size_t)NN * 128;
constexpr float  NEG_SLOPE = 0.22916666666666666f;

constexpr size_t O_HW1  = 0;
constexpr size_t O_G    = 1 * ND;
constexpr size_t O_SELF = 2 * ND;
constexpr size_t O_ISO  = 3 * ND;
constexpr size_t O_WSUM = 4 * ND;
constexpr size_t O_S    = 5 * ND;
constexpr size_t O_SW1  = 6 * ND;
constexpr size_t O_H1   = 7 * ND;
constexpr size_t O_SCORE = 8 * ND;
constexpr size_t O_SMAX  = O_SCORE + NE;
constexpr size_t O_DEN   = O_SMAX + NN;
constexpr size_t O_DEG   = O_DEN + NN;
constexpr size_t SCRATCH = O_DEG + NN;

// GEMM smem layout (bytes). Tile rows padded: 128 bf16 data + 8 pad = 136 elems
// = 272B per row -> ldmatrix row stride 68 words -> bank phase +4/row ->
// conflict-free 8-row reads.
constexpr int LDTB       = 272;            // bytes per padded tile row
constexpr int TILE_BYTES = 128 * LDTB;     // 34816
constexpr int SM_BIAS = 0;                 // 128 floats
constexpr int SA_HI = 512;
constexpr int SA_LO = SA_HI + TILE_BYTES;
constexpr int SB_HI = SA_LO + TILE_BYTES;
constexpr int SB_LO = SB_HI + TILE_BYTES;
constexpr int GEMM_SMEM = SB_LO + TILE_BYTES;   // 139,776 B
}  // namespace

__device__ float g_scratch[SCRATCH];

// ---------------------------------------------------------------------------
// warp-MMA helpers (sm_80+ instructions only)
// ---------------------------------------------------------------------------
__device__ __forceinline__ uint32_t smem_u32(const void* p) {
    uint32_t a;
    asm("{ .reg .u64 t; cvta.to.shared.u64 t, %1; cvt.u32.u64 %0, t; }" : "=r"(a) : "l"(p));
    return a;
}
__device__ __forceinline__ void ldsm_x4(uint32_t* r, uint32_t addr) {
    asm volatile("ldmatrix.sync.aligned.m8n8.x4.shared.b16 {%0,%1,%2,%3}, [%4];"
                 : "=r"(r[0]), "=r"(r[1]), "=r"(r[2]), "=r"(r[3]) : "r"(addr));
}
__device__ __forceinline__ void ldsm_x2t(uint32_t* r, uint32_t addr) {
    asm volatile("ldmatrix.sync.aligned.m8n8.x2.trans.shared.b16 {%0,%1}, [%2];"
                 : "=r"(r[0]), "=r"(r[1]) : "r"(addr));
}
__device__ __forceinline__ void ldsm_x2(uint32_t* r, uint32_t addr) {
    asm volatile("ldmatrix.sync.aligned.m8n8.x2.shared.b16 {%0,%1}, [%2];"
                 : "=r"(r[0]), "=r"(r[1]) : "r"(addr));
}
__device__ __forceinline__ void mma_bf16(float* d, const uint32_t* a, const uint32_t* b) {
    asm volatile("mma.sync.aligned.m16n8k16.row.col.f32.bf16.bf16.f32 "
                 "{%0,%1,%2,%3}, {%4,%5,%6,%7}, {%8,%9}, {%0,%1,%2,%3};"
                 : "+f"(d[0]), "+f"(d[1]), "+f"(d[2]), "+f"(d[3])
                 : "r"(a[0]), "r"(a[1]), "r"(a[2]), "r"(a[3]), "r"(b[0]), "r"(b[1]));
}

// fp32 -> bf16 hi + bf16 lo(residual), stored to padded row-major tile
__device__ __forceinline__ void split_store(char* hiB, char* loB, uint32_t off, float4 v) {
    __nv_bfloat162 h01 = __float22bfloat162_rn(make_float2(v.x, v.y));
    __nv_bfloat162 h23 = __float22bfloat162_rn(make_float2(v.z, v.w));
    float2 f01 = __bfloat1622float2(h01);
    float2 f23 = __bfloat1622float2(h23);
    __nv_bfloat162 l01 = __float22bfloat162_rn(make_float2(v.x - f01.x, v.y - f01.y));
    __nv_bfloat162 l23 = __float22bfloat162_rn(make_float2(v.z - f23.x, v.w - f23.y));
    *reinterpret_cast<__nv_bfloat162*>(hiB + off)     = h01;
    *reinterpret_cast<__nv_bfloat162*>(hiB + off + 4) = h23;
    *reinterpret_cast<__nv_bfloat162*>(loB + off)     = l01;
    *reinterpret_cast<__nv_bfloat162*>(loB + off + 4) = l23;
}

// ---------------------------------------------------------------------------
// tensor-core GEMM: C[M,128] = A[M,128] @ Wmath + bias
// WKN=1: Wmath = W as stored [k][n]      (C = A @ W)
// WKN=0: Wmath = W^T, W stored [n][k]    (C = A @ W^T)
// Either way W's rows are copied contiguously into smem; only the ldmatrix
// addressing differs (trans for [k][n], non-trans for [n][k] col-major B).
// ---------------------------------------------------------------------------
template <int WKN>
__global__ __launch_bounds__(256, 1)
void tc_gemm(const float* __restrict__ A, const float* __restrict__ W,
             const float* __restrict__ bias, float* __restrict__ C, int M)
{
    extern __shared__ char smem[];
    const uint32_t sb = smem_u32(smem);
    const int tid = threadIdx.x, wid = tid >> 5, lane = tid & 31;
    const int row0 = blockIdx.x * 128;

    if (tid < 128)
        reinterpret_cast<float*>(smem + SM_BIAS)[tid] = bias ? bias[tid] : 0.f;

    // fill A tile (zero-pad invalid rows)
    {
        const int r = tid >> 1, ch = (tid & 1) << 6;
        const bool valid = (row0 + r) < M;
        const float4* ap = reinterpret_cast<const float4*>(A + (size_t)(row0 + r) * 128 + ch);
#pragma unroll
        for (int i = 0; i < 16; ++i) {
            float4 v = valid ? __ldg(ap + i) : make_float4(0.f, 0.f, 0.f, 0.f);
            split_store(smem + SA_HI, smem + SA_LO, r * LDTB + (ch + i * 4) * 2, v);
        }
    }
    // fill B tile: rows of W -> rows of smem (contiguous in both modes)
    {
        const int r = tid >> 1, ch = (tid & 1) << 6;
        const float4* wp = reinterpret_cast<const float4*>(W + (size_t)r * 128 + ch);
#pragma unroll
        for (int i = 0; i < 16; ++i) {
            float4 v = __ldg(wp + i);
            split_store(smem + SB_HI, smem + SB_LO, r * LDTB + (ch + i * 4) * 2, v);
        }
    }
    __syncthreads();

    const int mw = (wid & 3) * 32;   // warp row offset in tile
    const int nw = (wid >> 2) * 64;  // warp col offset in tile

    float acc[2][8][4];
#pragma unroll
    for (int mt = 0; mt < 2; ++mt)
#pragma unroll
        for (int nt = 0; nt < 8; ++nt)
#pragma unroll
            for (int j = 0; j < 4; ++j) acc[mt][nt][j] = 0.f;

    // pre-computed intra-warp fragment addresses
    const uint32_t a_row_off = (mw + (lane & 15)) * LDTB + ((lane >> 4) << 3) * 2;
    const uint32_t bt_row    = (lane & 15) * LDTB;               // trans path
    const uint32_t bn_off    = (lane & 7) * LDTB + (((lane >> 3) & 1) << 3) * 2;  // non-trans

#pragma unroll
    for (int g = 0; g < 3; ++g) {
        const uint32_t abase = sb + (g == 2 ? SA_LO : SA_HI);
        const uint32_t bbase = sb + (g == 1 ? SB_LO : SB_HI);
#pragma unroll
        for (int kk = 0; kk < 8; ++kk) {
            uint32_t a[2][4];
            ldsm_x4(a[0], abase + a_row_off + kk * 32);
            ldsm_x4(a[1], abase + a_row_off + 16 * LDTB + kk * 32);
            uint32_t b[8][2];
#pragma unroll
            for (int nt = 0; nt < 8; ++nt) {
                if (WKN)   // B stored [k][n]: trans load at row k, col n
                    ldsm_x2t(b[nt], bbase + kk * 16 * LDTB + bt_row + (nw + nt * 8) * 2);
                else       // B stored [n][k]: non-trans load at row n, col k
                    ldsm_x2(b[nt], bbase + (nw + nt * 8) * LDTB + bn_off + kk * 32);
            }
#pragma unroll
            for (int mt = 0; mt < 2; ++mt)
#pragma unroll
                for (int nt = 0; nt < 8; ++nt)
                    mma_bf16(acc[mt][nt], a[mt], b[nt]);
        }
    }

    // epilogue: c frag -> thread holds rows (lane>>2, +8), cols 2*(lane&3)+{0,1}
    const float* bs = reinterpret_cast<const float*>(smem + SM_BIAS);
    const int rq = lane >> 2, c2 = (lane & 3) * 2;
#pragma unroll
    for (int mt = 0; mt < 2; ++mt) {
        const int r0 = row0 + mw + mt * 16 + rq;
#pragma unroll
        for (int nt = 0; nt < 8; ++nt) {
            const int col = nw + nt * 8 + c2;
            const float bx = bs[col], by = bs[col + 1];
            if (r0 < M)
                *reinterpret_cast<float2*>(C + (size_t)r0 * 128 + col) =
                    make_float2(acc[mt][nt][0] + bx, acc[mt][nt][1] + by);
            if (r0 + 8 < M)
                *reinterpret_cast<float2*>(C + (size_t)(r0 + 8) * 128 + col) =
                    make_float2(acc[mt][nt][2] + bx, acc[mt][nt][3] + by);
        }
    }
}

// ---------------------------------------------------------------------------
// small helpers
// ---------------------------------------------------------------------------
__global__ void zero_int_kernel(int* p, int n)
{
    int i = blockIdx.x * blockDim.x + threadIdx.x;
    if (i < n) p[i] = 0;
}

__global__ void deg_kernel(const int* __restrict__ dst, int* __restrict__ deg)
{
    int e = blockIdx.x * blockDim.x + threadIdx.x;
    if (e < NE) atomicAdd(deg + dst[e], 1);
}

__global__ void init_layer_kernel(float* __restrict__ wsumh, float* __restrict__ sbuf,
                                  float* __restrict__ denom, unsigned int* __restrict__ smax)
{
    size_t i = (size_t)blockIdx.x * blockDim.x + threadIdx.x;
    if (i < ND) { wsumh[i] = 0.f; sbuf[i] = 0.f; }
    if (i < NN) { denom[i] = 0.f; smax[i] = 0u; }
}

// ---------------------------------------------------------------------------
// pass 1: per-edge score + segment max (one warp per edge)
// ---------------------------------------------------------------------------
__global__ __launch_bounds__(256) void pass1_kernel(
    const float* __restrict__ h, const float* __restrict__ hW1,
    const float* __restrict__ g, const float* __restrict__ ef,
    const int* __restrict__ src, const int* __restrict__ dst,
    float* __restrict__ score, unsigned int* __restrict__ smax)
{
    int gt = blockIdx.x * blockDim.x + threadIdx.x;
    int e = gt >> 5;
    if (e >= NE) return;
    int lane = gt & 31;
    int s = __ldg(src + e), d = __ldg(dst + e);

    float4 hd = __ldg(reinterpret_cast<const float4*>(h)   + d * 32 + lane);
    float4 hw = __ldg(reinterpret_cast<const float4*>(hW1) + s * 32 + lane);
    float4 gd = __ldg(reinterpret_cast<const float4*>(g)   + d * 32 + lane);
    float4 ev = __ldg(reinterpret_cast<const float4*>(ef)  + (size_t)e * 32 + lane);

    float p = hd.x * hw.x + hd.y * hw.y + hd.z * hw.z + hd.w * hw.w
            + gd.x * ev.x + gd.y * ev.y + gd.z * ev.z + gd.w * ev.w;
#pragma unroll
    for (int o = 16; o > 0; o >>= 1) p += __shfl_xor_sync(0xffffffffu, p, o);

    if (lane == 0) {
        score[e] = p;
        unsigned u = __float_as_uint(p);
        u = (u & 0x80000000u) ? ~u : (u | 0x80000000u);
        atomicMax(smax + d, u);
    }
}

// ---------------------------------------------------------------------------
// pass 2: w = exp(score - smax); scatter w*hW1[src], w*efeat via red.v4
// ---------------------------------------------------------------------------
__device__ __forceinline__ void red4(float* p, float a, float b, float c, float d)
{
    asm volatile("red.global.add.v4.f32 [%0], {%1,%2,%3,%4};"
                 :: "l"(p), "f"(a), "f"(b), "f"(c), "f"(d) : "memory");
}

__global__ __launch_bounds__(256) void pass2_kernel(
    const float* __restrict__ hW1, const float* __restrict__ ef,
    const int* __restrict__ src, const int* __restrict__ dst,
    const float* __restrict__ score, const unsigned int* __restrict__ smax,
    float* __restrict__ denom, float* __restrict__ wsumh, float* __restrict__ sbuf)
{
    int gt = blockIdx.x * blockDim.x + threadIdx.x;
    int e = gt >> 5;
    if (e >= NE) return;
    int lane = gt & 31;
    int s = __ldg(src + e), d = __ldg(dst + e);

    unsigned mu = __ldg(smax + d);
    float mx = (mu & 0x80000000u) ? __uint_as_float(mu ^ 0x80000000u)
                                  : __uint_as_float(~mu);
    float w = __expf(__ldg(score + e) - mx);
    if (lane == 0) atomicAdd(denom + d, w);

    float4 hw = __ldg(reinterpret_cast<const float4*>(hW1) + s * 32 + lane);
    float4 ev = __ldg(reinterpret_cast<const float4*>(ef)  + (size_t)e * 32 + lane);

    red4(wsumh + (size_t)d * 128 + lane * 4, w * hw.x, w * hw.y, w * hw.z, w * hw.w);
    red4(sbuf  + (size_t)d * 128 + lane * 4, w * ev.x, w * ev.y, w * ev.z, w * ev.w);
}

// ---------------------------------------------------------------------------
// finalize
// ---------------------------------------------------------------------------
__device__ __forceinline__ float lrelu(float v) { return v >= 0.f ? v : v * NEG_SLOPE; }

__global__ __launch_bounds__(256) void finalize_kernel(
    const float* __restrict__ wsumh, const float* __restrict__ sW1,
    const float* __restrict__ denom, const int* __restrict__ deg,
    const float* __restrict__ selfm, const float* __restrict__ isom,
    float* __restrict__ out)
{
    int i = blockIdx.x * blockDim.x + threadIdx.x;
    if (i >= NN * 32) return;
    int n = i >> 5;

    float4 ws = __ldg(reinterpret_cast<const float4*>(wsumh) + i);
    float4 sv = __ldg(reinterpret_cast<const float4*>(sW1)   + i);
    float inv = 1.0f / fmaxf(__ldg(denom + n), 1e-30f);
    const float4* smp = (__ldg(deg + n) == 0)
                            ? reinterpret_cast<const float4*>(isom)
                            : reinterpret_cast<const float4*>(selfm);
    float4 sm = __ldg(smp + i);

    float4 r;
    r.x = lrelu(sm.x + (ws.x + sv.x) * inv);
    r.y = lrelu(sm.y + (ws.y + sv.y) * inv);
    r.z = lrelu(sm.z + (ws.z + sv.z) * inv);
    r.w = lrelu(sm.w + (ws.w + sv.w) * inv);
    reinterpret_cast<float4*>(out)[i] = r;
}

// ---------------------------------------------------------------------------
// launch
// ---------------------------------------------------------------------------
extern "C" void kernel_launch(void* const* d_in, const int* in_sizes, int n_in,
                              void* d_out, int out_size)
{
    const float* node = (const float*)d_in[0];
    const float* ef   = (const float*)d_in[1];
    const int*   src  = (const int*)d_in[2];
    const int*   dst  = (const int*)d_in[3];
    const float* W1[2] = {(const float*)d_in[4],  (const float*)d_in[10]};
    const float* B1[2] = {(const float*)d_in[5],  (const float*)d_in[11]};
    const float* W2[2] = {(const float*)d_in[6],  (const float*)d_in[12]};
    const float* B2[2] = {(const float*)d_in[7],  (const float*)d_in[13]};
    const float* W3[2] = {(const float*)d_in[8],  (const float*)d_in[14]};
    const float* B3[2] = {(const float*)d_in[9],  (const float*)d_in[15]};

    float* base = nullptr;
    cudaGetSymbolAddress((void**)&base, g_scratch);

    float*        hW1   = base + O_HW1;
    float*        g     = base + O_G;
    float*        selfm = base + O_SELF;
    float*        isom  = base + O_ISO;
    float*        wsumh = base + O_WSUM;
    float*        sbuf  = base + O_S;
    float*        sW1   = base + O_SW1;
    float*        h1    = base + O_H1;
    float*        score = base + O_SCORE;
    unsigned int* smax  = (unsigned int*)(base + O_SMAX);
    float*        denom = base + O_DEN;
    int*          deg   = (int*)(base + O_DEG);

    cudaFuncSetAttribute(tc_gemm<1>, cudaFuncAttributeMaxDynamicSharedMemorySize, GEMM_SMEM);
    cudaFuncSetAttribute(tc_gemm<0>, cudaFuncAttributeMaxDynamicSharedMemorySize, GEMM_SMEM);

    zero_int_kernel<<<(NN + 255) / 256, 256>>>(deg, NN);
    deg_kernel<<<(NE + 255) / 256, 256>>>(dst, deg);

    const int gemmGrid = (NN + 127) / 128;                      // 391
    const int edgeGrid = (int)(((size_t)NE * 32 + 255) / 256);  // 75000
    const int initGrid = (int)((ND + 255) / 256);

    const float* h = node;
    float* out_l[2] = {h1, (float*)d_out};

    for (int l = 0; l < 2; ++l) {
        init_layer_kernel<<<initGrid, 256>>>(wsumh, sbuf, denom, smax);

        tc_gemm<1><<<gemmGrid, 256, GEMM_SMEM>>>(h, W1[l], B1[l], hW1,   NN);
        tc_gemm<0><<<gemmGrid, 256, GEMM_SMEM>>>(h, W1[l], nullptr, g,   NN);  // h @ W1^T
        tc_gemm<1><<<gemmGrid, 256, GEMM_SMEM>>>(h, W2[l], B2[l], selfm, NN);
        tc_gemm<1><<<gemmGrid, 256, GEMM_SMEM>>>(h, W3[l], B3[l], isom,  NN);

        pass1_kernel<<<edgeGrid, 256>>>(h, hW1, g, ef, src, dst, score, smax);
        pass2_kernel<<<edgeGrid, 256>>>(hW1, ef, src, dst, score, smax, denom, wsumh, sbuf);

        tc_gemm<1><<<gemmGrid, 256, GEMM_SMEM>>>(sbuf, W1[l], nullptr, sW1, NN);

        finalize_kernel<<<(NN * 32 + 255) / 256, 256>>>(wsumh, sW1, denom, deg,
                                                        selfm, isom, out_l[l]);
        h = h1;
    }
}